// round 5
// baseline (speedup 1.0000x reference)
#include <cuda_runtime.h>
#include <cuda_bf16.h>

#define N_NODES 50000
#define N_EDGES 800000
#define D       64
#define ROWS    128                    // rows per block in the dense kernel
#define SBLK    1024                   // scan block size
#define NSB     ((N_NODES + SBLK - 1) / SBLK)   // 49 scan blocks

// Scratch (__device__ globals; zero-initialized at module load).
// Invariant: g_cnt is all-zero on entry (scan pass 3 restores it).
__device__ int   g_cnt[N_NODES];
__device__ int   g_off[N_NODES + 1];
__device__ int   g_ctr[N_NODES];
__device__ int   g_bsum[NSB];
__device__ int   g_bofs[NSB];
__device__ int2  g_edge[N_EDGES];      // {src, float_as_int(w)} sorted by dst
__device__ float g_neigh[N_NODES * D];

// packed fp32x2 FMA: d = a*b + d   (Blackwell double-rate fp32 path)
__device__ __forceinline__ void ffma2(unsigned long long& d,
                                      unsigned long long a,
                                      unsigned long long b) {
    asm("fma.rn.f32x2 %0, %1, %2, %0;" : "+l"(d) : "l"(a), "l"(b));
}
__device__ __forceinline__ unsigned long long pack2(float x) {
    unsigned long long r;
    unsigned int xi = __float_as_uint(x);
    asm("mov.b64 %0, {%1, %1};" : "=l"(r) : "r"(xi));
    return r;
}
__device__ __forceinline__ void unpack2(unsigned long long v, float& lo, float& hi) {
    unsigned int a, b;
    asm("mov.b64 {%0, %1}, %2;" : "=r"(a), "=r"(b) : "l"(v));
    lo = __uint_as_float(a);
    hi = __uint_as_float(b);
}

// ---------------------------------------------------------------------------
// K1: histogram of edge destinations (spread atomics, L2-resident)
// ---------------------------------------------------------------------------
__global__ void hist_kernel(const int* __restrict__ dst) {
    int t = blockIdx.x * blockDim.x + threadIdx.x;
    if (t < N_EDGES) atomicAdd(&g_cnt[dst[t]], 1);
}

// ---------------------------------------------------------------------------
// K2a: per-block sums of g_cnt (coalesced) -> g_bsum
// ---------------------------------------------------------------------------
__global__ __launch_bounds__(SBLK)
void scan_bsum_kernel() {
    __shared__ int s[32];
    int t = threadIdx.x;
    int idx = blockIdx.x * SBLK + t;
    int v = (idx < N_NODES) ? g_cnt[idx] : 0;
#pragma unroll
    for (int off = 16; off > 0; off >>= 1)
        v += __shfl_down_sync(0xffffffffu, v, off);
    if ((t & 31) == 0) s[t >> 5] = v;
    __syncthreads();
    if (t < 32) {
        int x = s[t];
#pragma unroll
        for (int off = 16; off > 0; off >>= 1)
            x += __shfl_down_sync(0xffffffffu, x, off);
        if (t == 0) g_bsum[blockIdx.x] = x;
    }
}

// ---------------------------------------------------------------------------
// K2b: exclusive scan of the NSB block sums (tiny)
// ---------------------------------------------------------------------------
__global__ void scan_tops_kernel() {
    __shared__ int s[NSB];
    int t = threadIdx.x;
    if (t < NSB) s[t] = g_bsum[t];
    __syncthreads();
    if (t == 0) {
        int acc = 0;
        for (int i = 0; i < NSB; i++) { int c = s[i]; s[i] = acc; acc += c; }
    }
    __syncthreads();
    if (t < NSB) g_bofs[t] = s[t];
}

// ---------------------------------------------------------------------------
// K2c: per-block exclusive scan (shfl-based, 2 barriers), add block prefix,
// write offsets + working counters coalesced, re-zero counts.
// ---------------------------------------------------------------------------
__global__ __launch_bounds__(SBLK)
void scan_local_kernel() {
    __shared__ int wsum[32];
    int t    = threadIdx.x;
    int lane = t & 31;
    int wid  = t >> 5;
    int idx  = blockIdx.x * SBLK + t;
    int c = (idx < N_NODES) ? g_cnt[idx] : 0;

    // warp inclusive scan
    int v = c;
#pragma unroll
    for (int off = 1; off < 32; off <<= 1) {
        int u = __shfl_up_sync(0xffffffffu, v, off);
        if (lane >= off) v += u;
    }
    if (lane == 31) wsum[wid] = v;
    __syncthreads();
    if (wid == 0) {
        int x = wsum[lane];
#pragma unroll
        for (int off = 1; off < 32; off <<= 1) {
            int u = __shfl_up_sync(0xffffffffu, x, off);
            if (lane >= off) x += u;
        }
        wsum[lane] = x;
    }
    __syncthreads();
    int warpPrefix = (wid > 0) ? wsum[wid - 1] : 0;
    int excl = g_bofs[blockIdx.x] + warpPrefix + v - c;

    if (idx < N_NODES) {
        g_off[idx] = excl;
        g_ctr[idx] = excl;
        g_cnt[idx] = 0;                         // restore invariant
    }
    if (idx == N_NODES - 1) g_off[N_NODES] = N_EDGES;
}

// ---------------------------------------------------------------------------
// K3: reorder edges into dst-sorted order (counting-sort scatter phase)
// ---------------------------------------------------------------------------
__global__ void reorder_kernel(const int*   __restrict__ src,
                               const int*   __restrict__ dst,
                               const float* __restrict__ w) {
    int t = blockIdx.x * blockDim.x + threadIdx.x;
    if (t >= N_EDGES) return;
    int d = dst[t];
    int p = atomicAdd(&g_ctr[d], 1);
    g_edge[p] = make_int2(src[t], __float_as_int(w[t]));
}

// ---------------------------------------------------------------------------
// K4: gather-side segment reduce. One warp per node; lane l owns dims
// 2l, 2l+1. Edge meta staged 32-at-a-time in per-warp smem; inner loop
// preloads 8 rows (MLP=8) before any FMA to hide L2 latency.
// ---------------------------------------------------------------------------
#define GW 8   // warps per gather block
__global__ __launch_bounds__(GW * 32)
void gather_kernel(const float* __restrict__ h) {
    __shared__ int2 sE[GW][32];
    int wslot = threadIdx.x >> 5;
    int warp  = (blockIdx.x * blockDim.x + threadIdx.x) >> 5;
    int lane  = threadIdx.x & 31;
    if (warp >= N_NODES) return;

    int beg = g_off[warp];
    int end = g_off[warp + 1];

    float2 acc = make_float2(0.f, 0.f);
    const float* hl = h + 2 * lane;

    for (int e0 = beg; e0 < end; e0 += 32) {
        int n = min(32, end - e0);
        if (lane < n) sE[wslot][lane] = g_edge[e0 + lane];
        __syncwarp();
        int j = 0;
        for (; j + 8 <= n; j += 8) {
            float2 hv[8];
            float  ww[8];
#pragma unroll
            for (int q = 0; q < 8; q++) {
                int2 e = sE[wslot][j + q];
                ww[q] = __int_as_float(e.y);
                hv[q] = *reinterpret_cast<const float2*>(hl + (size_t)e.x * D);
            }
#pragma unroll
            for (int q = 0; q < 8; q++) {
                acc.x = fmaf(ww[q], hv[q].x, acc.x);
                acc.y = fmaf(ww[q], hv[q].y, acc.y);
            }
        }
        if (j < n) {
            float2 hv[7];
            float  ww[7];
            int m = n - j;
#pragma unroll
            for (int q = 0; q < 7; q++) {
                if (q < m) {
                    int2 e = sE[wslot][j + q];
                    ww[q] = __int_as_float(e.y);
                    hv[q] = *reinterpret_cast<const float2*>(hl + (size_t)e.x * D);
                }
            }
#pragma unroll
            for (int q = 0; q < 7; q++) {
                if (q < m) {
                    acc.x = fmaf(ww[q], hv[q].x, acc.x);
                    acc.y = fmaf(ww[q], hv[q].y, acc.y);
                }
            }
        }
        __syncwarp();
    }
    *reinterpret_cast<float2*>(g_neigh + (size_t)warp * D + 2 * lane) = acc;
}

// ---------------------------------------------------------------------------
// K5: dense  out = relu([h | neigh] @ [W_self | W_neigh]^T + b_self + b_neigh)
// One thread per row; 64 accumulators packed as 32 b64 regs via fma.rn.f32x2
// (2 fp32 FMAs per issue). Weight pairs: broadcast LDS.128. kk unroll kept
// at 2 to bound live registers (round-2 attempt likely spilled at unroll 4).
// ---------------------------------------------------------------------------
__global__ __launch_bounds__(ROWS)
void dense_kernel(const float* __restrict__ h,
                  const float* __restrict__ Ws, const float* __restrict__ bs,
                  const float* __restrict__ Wn, const float* __restrict__ bn,
                  float* __restrict__ out) {
    __shared__ __align__(16) float sW[128 * 64];  // sW[k*64+j]
    __shared__ float sX[32][ROWS + 1];
    __shared__ float sB[64];

    const int tid     = threadIdx.x;
    const int rowBase = blockIdx.x * ROWS;
    const int row     = rowBase + tid;
    const bool valid  = row < N_NODES;

    for (int idx = tid; idx < 128 * 64; idx += ROWS) {
        int k = idx >> 6, j = idx & 63;
        sW[idx] = (k < 64) ? Ws[j * 64 + k] : Wn[j * 64 + (k - 64)];
    }
    if (tid < 64) sB[tid] = bs[tid] + bn[tid];

    unsigned long long acc[32];
#pragma unroll
    for (int p = 0; p < 32; p++) acc[p] = 0ull;

    const int lane = tid & 31;
    const int rq   = tid >> 5;

    for (int kc = 0; kc < 4; kc++) {
        const float* srcp = (kc < 2) ? h : g_neigh;
        const int colBase = (kc & 1) * 32;

        __syncthreads();

        for (int r = rq; r < ROWS; r += ROWS / 32) {
            int rr = rowBase + r;
            float val = (rr < N_NODES) ? srcp[(size_t)rr * D + colBase + lane] : 0.f;
            sX[lane][r] = val;
        }
        __syncthreads();

#pragma unroll 2
        for (int kk = 0; kk < 32; kk++) {
            unsigned long long xx = pack2(sX[kk][tid]);
            const ulonglong2* wrow = reinterpret_cast<const ulonglong2*>(
                sW + (kc * 32 + kk) * 64);
#pragma unroll
            for (int q = 0; q < 16; q++) {
                ulonglong2 wv = wrow[q];      // broadcast LDS.128 -> 2 packed pairs
                ffma2(acc[2 * q + 0], xx, wv.x);
                ffma2(acc[2 * q + 1], xx, wv.y);
            }
        }
    }

    if (valid) {
        float4* op = reinterpret_cast<float4*>(out + (size_t)row * D);
#pragma unroll
        for (int q4 = 0; q4 < 16; q4++) {
            float a, b, c, d;
            unpack2(acc[2 * q4 + 0], a, b);
            unpack2(acc[2 * q4 + 1], c, d);
            float4 o;
            o.x = fmaxf(a + sB[4 * q4 + 0], 0.f);
            o.y = fmaxf(b + sB[4 * q4 + 1], 0.f);
            o.z = fmaxf(c + sB[4 * q4 + 2], 0.f);
            o.w = fmaxf(d + sB[4 * q4 + 3], 0.f);
            op[q4] = o;
        }
    }
}

// ---------------------------------------------------------------------------
// kernel_launch
//   0: h [N,D] f32   1: edge_src [E] i32   2: edge_dst [E] i32   3: edge_w [E] f32
//   4: W_self [D,D]  5: b_self [D]         6: W_neigh [D,D]      7: b_neigh [D]
// ---------------------------------------------------------------------------
extern "C" void kernel_launch(void* const* d_in, const int* in_sizes, int n_in,
                              void* d_out, int out_size) {
    const float* h        = (const float*)d_in[0];
    const int*   edge_src = (const int*)  d_in[1];
    const int*   edge_dst = (const int*)  d_in[2];
    const float* edge_w   = (const float*)d_in[3];
    const float* W_self   = (const float*)d_in[4];
    const float* b_self   = (const float*)d_in[5];
    const float* W_neigh  = (const float*)d_in[6];
    const float* b_neigh  = (const float*)d_in[7];
    float* out = (float*)d_out;

    const int eb = (N_EDGES + 255) / 256;

    hist_kernel<<<eb, 256>>>(edge_dst);
    scan_bsum_kernel<<<NSB, SBLK>>>();
    scan_tops_kernel<<<1, 64>>>();
    scan_local_kernel<<<NSB, SBLK>>>();
    reorder_kernel<<<eb, 256>>>(edge_src, edge_dst, edge_w);

    {
        int blocks = (N_NODES + GW - 1) / GW;
        gather_kernel<<<blocks, GW * 32>>>(h);
    }

    {
        int blocks = (N_NODES + ROWS - 1) / ROWS;
        dense_kernel<<<blocks, ROWS>>>(h, W_self, b_self, W_neigh, b_neigh, out);
    }
}